// round 1
// baseline (speedup 1.0000x reference)
#include <cuda_runtime.h>

// QueryEncDec: 2x128-layer scalar GRU (H=in=1), T=256.
// Encoder+decoder fused into one 256-layer wavefront: thread = global layer,
// diagonal steps pass layer outputs through double-buffered shared memory.
//
// out[0:256]   = dec_out (outputs of global layer 255 at each t)
// out[256:384] = dec_h   (final hidden h[T-1] of global layers 128..255)

#define GRU_T   256
#define GRU_LT  256   // total layers (enc 128 + dec 128)

__global__ __launch_bounds__(256, 1)
void gru_wavefront_kernel(const float* __restrict__ X,
                          const float* __restrict__ ewi, const float* __restrict__ ewh,
                          const float* __restrict__ ebi, const float* __restrict__ ebh,
                          const float* __restrict__ dwi, const float* __restrict__ dwh,
                          const float* __restrict__ dbi, const float* __restrict__ dbh,
                          float* __restrict__ out)
{
    const int l = threadIdx.x;            // global layer index 0..255

    __shared__ float xs[GRU_T];
    __shared__ float buf[2][GRU_LT];

    // Stage input sequence (X is [T,1] contiguous)
    xs[l] = X[l];

    // Per-layer scalar weights (torch gate order r,z,n)
    const bool enc = (l < 128);
    const int  li  = enc ? l : (l - 128);
    const float* wi = enc ? ewi : dwi;
    const float* wh = enc ? ewh : dwh;
    const float* bi = enc ? ebi : dbi;
    const float* bh = enc ? ebh : dbh;

    const float wi_r = wi[li*3+0], wi_z = wi[li*3+1], wi_n = wi[li*3+2];
    const float wh_r = wh[li*3+0], wh_z = wh[li*3+1], wh_n = wh[li*3+2];
    const float bi_r = bi[li*3+0], bi_z = bi[li*3+1], bi_n = bi[li*3+2];
    const float bh_r = bh[li*3+0], bh_z = bh[li*3+1], bh_n = bh[li*3+2];

    const float nwi_r = -wi_r;            // folded negations so the x-chain is
    const float nwi_z = -wi_z;            // fma -> exp with no extra neg
    const float sb_r  = bi_r + bh_r;      // bias sums (h-independent)
    const float sb_z  = bi_z + bh_z;

    float h = 0.0f;
    // h-dependent terms for the FIRST step (h = 0): hoisted off the x-chain
    float gh_n = bh_n;                    // wh_n*h + bh_n
    float nc_r = -sb_r;                   // -(bi_r + wh_r*h + bh_r)
    float nc_z = -sb_z;

    __syncthreads();

    #pragma unroll 1
    for (int d = 0; d < GRU_T + GRU_LT - 1; ++d) {
        const int t = d - l;
        if (t >= 0 && t < GRU_T) {
            // input: layer 0 reads X[t]; others read layer l-1's output
            // written last step into buf[(d-1)&1] == buf[(d+1)&1]
            const float x = (l == 0) ? xs[t] : buf[(d + 1) & 1][l - 1];

            // r = sigmoid(wi_r*x + bi_r + wh_r*h + bh_r)
            const float er = __expf(fmaf(nwi_r, x, nc_r));
            const float r  = __fdividef(1.0f, 1.0f + er);
            // z (independent MUFU chain, overlaps with r)
            const float ez = __expf(fmaf(nwi_z, x, nc_z));
            const float z  = __fdividef(1.0f, 1.0f + ez);
            // n = tanh(wi_n*x + bi_n + r*(wh_n*h + bh_n))
            float an = fmaf(wi_n, x, bi_n);
            an = fmaf(r, gh_n, an);
            const float e2 = __expf(-2.0f * an);
            const float n  = __fdividef(1.0f - e2, 1.0f + e2);
            // h' = (1-z)*n + z*h = z*(h-n) + n
            h = fmaf(z, h - n, n);

            buf[d & 1][l] = h;

            // tail: next step's h-dependent terms (off next x-chain)
            gh_n = fmaf(wh_n, h, bh_n);
            nc_r = -fmaf(wh_r, h, sb_r);
            nc_z = -fmaf(wh_z, h, sb_z);

            if (l == GRU_LT - 1)              out[t] = h;            // dec_out
            if (t == GRU_T - 1 && l >= 128)   out[GRU_T + (l - 128)] = h;  // dec_h
        }
        __syncthreads();
    }
}

extern "C" void kernel_launch(void* const* d_in, const int* in_sizes, int n_in,
                              void* d_out, int out_size)
{
    const float* X   = (const float*)d_in[0];
    const float* ewi = (const float*)d_in[1];
    const float* ewh = (const float*)d_in[2];
    const float* ebi = (const float*)d_in[3];
    const float* ebh = (const float*)d_in[4];
    const float* dwi = (const float*)d_in[5];
    const float* dwh = (const float*)d_in[6];
    const float* dbi = (const float*)d_in[7];
    const float* dbh = (const float*)d_in[8];
    float* out = (float*)d_out;

    gru_wavefront_kernel<<<1, 256>>>(X, ewi, ewh, ebi, ebh, dwi, dwh, dbi, dbh, out);
}